// round 1
// baseline (speedup 1.0000x reference)
#include <cuda_runtime.h>
#include <math.h>

// Problem constants
constexpr int CB  = 2;
constexpr int CS  = 2048;
constexpr int CE  = 512;
constexpr int CH  = 8;
constexpr int CBS = CB * CS;  // 4096

// Scratch (device globals -- allocation-free rule compliant)
__device__ __align__(128) float g_q[CBS * CE];
__device__ __align__(128) float g_k[CBS * CE];
__device__ __align__(128) float g_v[CBS * CE];
__device__ __align__(128) float g_scores[CB * CH * CS * CS];  // 268 MB
__device__ __align__(128) float g_wmean[CB * CS * CS];        // 33.5 MB
__device__ __align__(128) float g_wmaskn[CB * CS * CS];       // 33.5 MB
__device__ __align__(128) float g_msg[CBS * CE];
__device__ __align__(128) float g_att[CBS * CE];
__device__ __align__(128) float g_t1[CBS * CE];
__device__ __align__(128) float g_t2[CBS * CE];
__device__ __align__(128) float g_bm1eff[CE];

// ---------------------------------------------------------------------------
// Generic fp32 tiled GEMM: C = alpha * A @ op(B) (+bias[col]) (+add0) (+add1),
// optional exact GELU. A is [M x K] row-major. TRANSB: B is [N x K] row-major
// (C = A B^T); else B is [K x N] row-major.
// Tiles: 128x128x16, 256 threads, 8x8 per thread. M,N multiples of 128,
// K multiple of 16 (all shapes here satisfy this).
// ---------------------------------------------------------------------------
struct GemmP {
    const float* A; const float* B; float* C;
    int lda, ldb, ldc;
    int K;
    float alpha;
    const float* bias;
    const float* add0;
    const float* add1;
    int gelu;
    int zdiv;
    long long sAz, sAw, sBz, sBw, sCz, sCw;
};

template <bool TRANSB>
__global__ void __launch_bounds__(256) gemm_k(GemmP p) {
    const int z  = blockIdx.z;
    const int zq = z / p.zdiv;
    const int zr = z % p.zdiv;
    const float* A = p.A + (size_t)zq * p.sAz + (size_t)zr * p.sAw;
    const float* B = p.B + (size_t)zq * p.sBz + (size_t)zr * p.sBw;
    float*       C = p.C + (size_t)zq * p.sCz + (size_t)zr * p.sCw;
    const float* add0 = p.add0 ? p.add0 + (size_t)zq * p.sCz + (size_t)zr * p.sCw : nullptr;
    const float* add1 = p.add1 ? p.add1 + (size_t)zq * p.sCz + (size_t)zr * p.sCw : nullptr;

    __shared__ float As[16][128];
    __shared__ float Bs[16][128];

    const int tid = threadIdx.x;
    const int tx = tid & 15;        // 0..15 -> 8 cols each
    const int ty = tid >> 4;        // 0..15 -> 8 rows each
    const int rowBase = blockIdx.y * 128;
    const int colBase = blockIdx.x * 128;

    float acc[8][8];
#pragma unroll
    for (int i = 0; i < 8; i++)
#pragma unroll
        for (int j = 0; j < 8; j++) acc[i][j] = 0.f;

    for (int k0 = 0; k0 < p.K; k0 += 16) {
        // Load A tile (128 rows x 16 k) as float4 along k
#pragma unroll
        for (int i = 0; i < 2; i++) {
            int idx = tid * 2 + i;           // 0..511
            int r   = idx >> 2;              // 0..127
            int k4  = (idx & 3) << 2;        // 0,4,8,12
            float4 va = *(const float4*)&A[(size_t)(rowBase + r) * p.lda + k0 + k4];
            As[k4 + 0][r] = va.x; As[k4 + 1][r] = va.y;
            As[k4 + 2][r] = va.z; As[k4 + 3][r] = va.w;
        }
        if (TRANSB) {
#pragma unroll
            for (int i = 0; i < 2; i++) {
                int idx = tid * 2 + i;
                int r   = idx >> 2;
                int k4  = (idx & 3) << 2;
                float4 vb = *(const float4*)&B[(size_t)(colBase + r) * p.ldb + k0 + k4];
                Bs[k4 + 0][r] = vb.x; Bs[k4 + 1][r] = vb.y;
                Bs[k4 + 2][r] = vb.z; Bs[k4 + 3][r] = vb.w;
            }
        } else {
#pragma unroll
            for (int i = 0; i < 2; i++) {
                int idx = tid + i * 256;     // coalesced along columns
                int kk  = idx >> 5;          // 0..15
                int c4  = (idx & 31) << 2;   // 0..124
                float4 vb = *(const float4*)&B[(size_t)(k0 + kk) * p.ldb + colBase + c4];
                *(float4*)&Bs[kk][c4] = vb;
            }
        }
        __syncthreads();

#pragma unroll
        for (int kk = 0; kk < 16; kk++) {
            float4 a0 = *(const float4*)&As[kk][ty * 8];
            float4 a1 = *(const float4*)&As[kk][ty * 8 + 4];
            float4 b0 = *(const float4*)&Bs[kk][tx * 8];
            float4 b1 = *(const float4*)&Bs[kk][tx * 8 + 4];
            float ra[8] = {a0.x, a0.y, a0.z, a0.w, a1.x, a1.y, a1.z, a1.w};
            float rb[8] = {b0.x, b0.y, b0.z, b0.w, b1.x, b1.y, b1.z, b1.w};
#pragma unroll
            for (int i = 0; i < 8; i++)
#pragma unroll
                for (int j = 0; j < 8; j++) acc[i][j] += ra[i] * rb[j];
        }
        __syncthreads();
    }

    const float alpha = p.alpha;
#pragma unroll
    for (int i = 0; i < 8; i++) {
        int r = rowBase + ty * 8 + i;
#pragma unroll
        for (int j = 0; j < 8; j++) {
            int c = colBase + tx * 8 + j;
            float v = acc[i][j] * alpha;
            if (p.bias) v += p.bias[c];
            size_t off = (size_t)r * p.ldc + c;
            if (add0) v += add0[off];
            if (add1) v += add1[off];
            if (p.gelu) v = 0.5f * v * (1.0f + erff(v * 0.70710678118654752440f));
            C[off] = v;
        }
    }
}

// ---------------------------------------------------------------------------
// Softmax + head-mean + adjacency kernel. One block per (b, i) row.
// Values are register-resident (each thread owns j = tid + 256*u).
// ---------------------------------------------------------------------------
__device__ __forceinline__ float blockMax256(float v, float* red) {
#pragma unroll
    for (int o = 16; o; o >>= 1) v = fmaxf(v, __shfl_xor_sync(0xffffffffu, v, o));
    int w = threadIdx.x >> 5;
    if ((threadIdx.x & 31) == 0) red[w] = v;
    __syncthreads();
    if (threadIdx.x < 32) {
        float x = (threadIdx.x < 8) ? red[threadIdx.x] : -3.4e38f;
#pragma unroll
        for (int o = 4; o; o >>= 1) x = fmaxf(x, __shfl_xor_sync(0xffffffffu, x, o));
        if (threadIdx.x == 0) red[0] = x;
    }
    __syncthreads();
    float r = red[0];
    __syncthreads();
    return r;
}

__device__ __forceinline__ float blockSum256(float v, float* red) {
#pragma unroll
    for (int o = 16; o; o >>= 1) v += __shfl_xor_sync(0xffffffffu, v, o);
    int w = threadIdx.x >> 5;
    if ((threadIdx.x & 31) == 0) red[w] = v;
    __syncthreads();
    if (threadIdx.x < 32) {
        float x = (threadIdx.x < 8) ? red[threadIdx.x] : 0.f;
#pragma unroll
        for (int o = 4; o; o >>= 1) x += __shfl_xor_sync(0xffffffffu, x, o);
        if (threadIdx.x == 0) red[0] = x;
    }
    __syncthreads();
    float r = red[0];
    __syncthreads();
    return r;
}

__global__ void __launch_bounds__(256) softmax_kernel(const float* __restrict__ scores,
                                                      float* __restrict__ wmean,
                                                      float* __restrict__ wmaskn) {
    const int i = blockIdx.x;
    const int b = blockIdx.y;
    const int tid = threadIdx.x;
    __shared__ float red[8];

    float wa[8];
#pragma unroll
    for (int u = 0; u < 8; u++) wa[u] = 0.f;

    for (int h = 0; h < CH; h++) {
        const float* row = scores + (((size_t)(b * CH + h) * CS) + i) * CS;
        float vals[8];
        float lmax = -3.4e38f;
#pragma unroll
        for (int u = 0; u < 8; u++) {
            vals[u] = row[tid + 256 * u];
            lmax = fmaxf(lmax, vals[u]);
        }
        float m = blockMax256(lmax, red);
        float lsum = 0.f;
#pragma unroll
        for (int u = 0; u < 8; u++) {
            vals[u] = expf(vals[u] - m);
            lsum += vals[u];
        }
        float d = blockSum256(lsum, red);
        float inv = 1.0f / d;
#pragma unroll
        for (int u = 0; u < 8; u++) wa[u] += vals[u] * inv;
    }

    float cnt = 0.f;
#pragma unroll
    for (int u = 0; u < 8; u++) {
        float wm = wa[u] * (1.0f / CH);
        wa[u] = wm;
        cnt += (wm > 0.1f) ? 1.f : 0.f;
    }
    float nn = blockSum256(cnt, red);
    nn = fmaxf(nn, 1.0f);
    float invn = 1.0f / nn;

    float* wmr = wmean  + ((size_t)b * CS + i) * CS;
    float* wkr = wmaskn + ((size_t)b * CS + i) * CS;
#pragma unroll
    for (int u = 0; u < 8; u++) {
        int j = tid + 256 * u;
        float wm = wa[u];
        wmr[j] = wm;
        wkr[j] = (wm > 0.1f) ? wm * invn : 0.f;
    }
}

// bm1eff[e] = bm1[e] + (1/S) * sum_{c=E..E+H-1} Wm1[e, c]   (edge_features == 1/S)
__global__ void bm1eff_kernel(const float* __restrict__ Wm1,
                              const float* __restrict__ bm1,
                              float* __restrict__ out) {
    int e = threadIdx.x;
    if (e < CE) {
        float s = 0.f;
#pragma unroll
        for (int c = 0; c < CH; c++) s += Wm1[(size_t)e * (CE + CH) + CE + c];
        out[e] = bm1[e] + s * (1.0f / CS);
    }
}

// ---------------------------------------------------------------------------
// Host side
// ---------------------------------------------------------------------------
static void run_gemm(bool transb, const float* A, int lda, const float* B, int ldb,
                     float* C, int ldc, int M, int N, int K, float alpha,
                     const float* bias, const float* add0, const float* add1, int gelu,
                     int zcount, int zdiv,
                     long long sAz, long long sAw, long long sBz, long long sBw,
                     long long sCz, long long sCw) {
    GemmP p;
    p.A = A; p.B = B; p.C = C;
    p.lda = lda; p.ldb = ldb; p.ldc = ldc;
    p.K = K; p.alpha = alpha;
    p.bias = bias; p.add0 = add0; p.add1 = add1; p.gelu = gelu;
    p.zdiv = zdiv;
    p.sAz = sAz; p.sAw = sAw; p.sBz = sBz; p.sBw = sBw; p.sCz = sCz; p.sCw = sCw;
    dim3 grid(N / 128, M / 128, zcount), block(256);
    if (transb) gemm_k<true><<<grid, block>>>(p);
    else        gemm_k<false><<<grid, block>>>(p);
}

extern "C" void kernel_launch(void* const* d_in, const int* in_sizes, int n_in,
                              void* d_out, int out_size) {
    const float* x   = (const float*)d_in[0];
    const float* Wq  = (const float*)d_in[1];
    const float* bq  = (const float*)d_in[2];
    const float* Wk  = (const float*)d_in[3];
    const float* bk  = (const float*)d_in[4];
    const float* Wv  = (const float*)d_in[5];
    const float* bv  = (const float*)d_in[6];
    const float* Wm1 = (const float*)d_in[7];
    const float* bm1 = (const float*)d_in[8];
    const float* Wm2 = (const float*)d_in[9];
    const float* bm2 = (const float*)d_in[10];
    const float* Wo  = (const float*)d_in[11];
    const float* bo  = (const float*)d_in[12];
    float* out = (float*)d_out;

    float *q, *k, *v, *sc, *wm, *wk, *msg, *att, *t1, *t2, *b1e;
    cudaGetSymbolAddress((void**)&q,   g_q);
    cudaGetSymbolAddress((void**)&k,   g_k);
    cudaGetSymbolAddress((void**)&v,   g_v);
    cudaGetSymbolAddress((void**)&sc,  g_scores);
    cudaGetSymbolAddress((void**)&wm,  g_wmean);
    cudaGetSymbolAddress((void**)&wk,  g_wmaskn);
    cudaGetSymbolAddress((void**)&msg, g_msg);
    cudaGetSymbolAddress((void**)&att, g_att);
    cudaGetSymbolAddress((void**)&t1,  g_t1);
    cudaGetSymbolAddress((void**)&t2,  g_t2);
    cudaGetSymbolAddress((void**)&b1e, g_bm1eff);

    const long long SE = (long long)CS * CE;   // per-batch [S,E] stride
    const long long SS = (long long)CS * CS;   // per-batch/head [S,S] stride

    // 1-3: QKV projections   q/k/v = x @ W^T + b
    run_gemm(true, x, CE, Wq, CE, q, CE, CBS, CE, CE, 1.f, bq, nullptr, nullptr, 0,
             1, 1, 0, 0, 0, 0, 0, 0);
    run_gemm(true, x, CE, Wk, CE, k, CE, CBS, CE, CE, 1.f, bk, nullptr, nullptr, 0,
             1, 1, 0, 0, 0, 0, 0, 0);
    run_gemm(true, x, CE, Wv, CE, v, CE, CBS, CE, CE, 1.f, bv, nullptr, nullptr, 0,
             1, 1, 0, 0, 0, 0, 0, 0);

    // 4: per-(b,h) scores = (1/8) * q_h @ k_h^T   (z = b*8+h, zdiv=8)
    run_gemm(true, q, CE, k, CE, sc, CS, CS, CS, 64, 0.125f, nullptr, nullptr, nullptr, 0,
             CB * CH, CH,
             SE, 64,          // A: +b*S*E, +h*64
             SE, 64,          // B: same
             (long long)CH * SS, SS);  // C: +(b*8+h)*S*S

    // 5: softmax + head mean + adjacency threshold + neighbor normalization
    {
        dim3 grid(CS, CB), block(256);
        softmax_kernel<<<grid, block>>>(sc, wm, wk);
    }

    // 6: messages = wmaskn @ x (per batch);  7: attended = wmean @ v
    run_gemm(false, wk, CS, x, CE, msg, CE, CS, CE, CS, 1.f, nullptr, nullptr, nullptr, 0,
             CB, 1, SS, 0, SE, 0, SE, 0);
    run_gemm(false, wm, CS, v, CE, att, CE, CS, CE, CS, 1.f, nullptr, nullptr, nullptr, 0,
             CB, 1, SS, 0, SE, 0, SE, 0);

    // 8: effective bm1 (edge_features identically 1/S)
    bm1eff_kernel<<<1, 512>>>(Wm1, bm1, b1e);

    // 9: t1 = gelu(x @ Wm1[:, :E]^T + bm1eff)
    run_gemm(true, x, CE, Wm1, CE + CH, t1, CE, CBS, CE, CE, 1.f, b1e, nullptr, nullptr, 1,
             1, 1, 0, 0, 0, 0, 0, 0);

    // 10: t2 = t1 @ Wm2^T + bm2 + messages + attended
    run_gemm(true, t1, CE, Wm2, CE, t2, CE, CBS, CE, CE, 1.f, bm2, msg, att, 0,
             1, 1, 0, 0, 0, 0, 0, 0);

    // 11: out = t2 @ Wo^T + bo
    run_gemm(true, t2, CE, Wo, CE, out, CE, CBS, CE, CE, 1.f, bo, nullptr, nullptr, 0,
             1, 1, 0, 0, 0, 0, 0, 0);
}

// round 5
// speedup vs baseline: 2.5520x; 2.5520x over previous
#include <cuda_runtime.h>
#include <cuda_bf16.h>
#include <cstdint>
#include <math.h>

constexpr int CB = 2, CS = 2048, CE = 512, CH = 8, CBS = CB * CS;

// ---------------- scratch (device globals; allocation-free) ----------------
__device__ __align__(128) float g_scores[(size_t)CB * CH * CS * CS];  // 268 MB
__device__ __align__(128) __nv_bfloat16 g_xh[CBS * CE], g_xl[CBS * CE];
__device__ __align__(128) __nv_bfloat16 g_qh[CBS * CE], g_ql[CBS * CE];
__device__ __align__(128) __nv_bfloat16 g_kh[CBS * CE], g_kl[CBS * CE];
__device__ __align__(128) __nv_bfloat16 g_vh[CBS * CE], g_vl[CBS * CE];
__device__ __align__(128) __nv_bfloat16 g_t1h[CBS * CE], g_t1l[CBS * CE];
__device__ __align__(128) __nv_bfloat16 g_t2h[CBS * CE], g_t2l[CBS * CE];
__device__ __align__(128) __nv_bfloat16 g_wmh[(size_t)CB * CS * CS], g_wml[(size_t)CB * CS * CS];
__device__ __align__(128) __nv_bfloat16 g_wkh[(size_t)CB * CS * CS], g_wkl[(size_t)CB * CS * CS];
__device__ __align__(128) __nv_bfloat16 g_Wh[6 * CE * CE], g_Wl[6 * CE * CE];
__device__ __align__(128) float g_msg[CBS * CE], g_att[CBS * CE], g_bm1eff[CE];

// ---------------- low-level helpers ----------------
__device__ __forceinline__ uint32_t smem_u32(const void* p) {
    uint32_t a;
    asm("{ .reg .u64 t; cvta.to.shared.u64 t, %1; cvt.u32.u64 %0, t; }" : "=r"(a) : "l"(p));
    return a;
}
__device__ __forceinline__ void cpasync16(uint32_t dst, const void* src) {
    asm volatile("cp.async.ca.shared.global [%0], [%1], 16;" :: "r"(dst), "l"(src));
}
__device__ __forceinline__ void cpcommit() { asm volatile("cp.async.commit_group;"); }
template <int N> __device__ __forceinline__ void cpwait() {
    asm volatile("cp.async.wait_group %0;" :: "n"(N));
}
__device__ __forceinline__ void ldsm4(uint32_t* r, uint32_t a) {
    asm volatile("ldmatrix.sync.aligned.m8n8.x4.shared.b16 {%0,%1,%2,%3}, [%4];"
                 : "=r"(r[0]), "=r"(r[1]), "=r"(r[2]), "=r"(r[3]) : "r"(a));
}
__device__ __forceinline__ void ldsm4t(uint32_t* r, uint32_t a) {
    asm volatile("ldmatrix.sync.aligned.m8n8.x4.trans.shared.b16 {%0,%1,%2,%3}, [%4];"
                 : "=r"(r[0]), "=r"(r[1]), "=r"(r[2]), "=r"(r[3]) : "r"(a));
}
__device__ __forceinline__ void mma16816(float* c, const uint32_t* a, const uint32_t* b) {
    asm volatile(
        "mma.sync.aligned.m16n8k16.row.col.f32.bf16.bf16.f32 "
        "{%0,%1,%2,%3}, {%4,%5,%6,%7}, {%8,%9}, {%0,%1,%2,%3};"
        : "+f"(c[0]), "+f"(c[1]), "+f"(c[2]), "+f"(c[3])
        : "r"(a[0]), "r"(a[1]), "r"(a[2]), "r"(a[3]), "r"(b[0]), "r"(b[1]));
}
__device__ __forceinline__ void split2(float v, __nv_bfloat16& h, __nv_bfloat16& l) {
    h = __float2bfloat16(v);
    l = __float2bfloat16(v - __bfloat162float(h));
}

// ---------------- bf16-split tensor-core GEMM ----------------
// C = alpha * A @ op(B) (+bias)(+adds)(gelu). A:[M][K] rm. TRANSB: B:[N][K] rm, else B:[K][N] rm.
// CTA tile 128x128, K-chunk 32, 2-stage cp.async pipeline, 8 warps of 64x32.
struct MP {
    const __nv_bfloat16 *Ah, *Al, *Bh, *Bl;
    int lda, ldb, K;
    float alpha;
    const float *bias, *add0, *add1;
    float* outF;
    __nv_bfloat16 *outHi, *outLo;
    int ldc, gelu, zdiv;
    long long sAz, sAw, sBz, sBw, sCz, sCw;
};

constexpr int STG = 12288;          // bytes per buffer per stage
constexpr int SMEM_BYTES = 8 * STG; // 98304

// A/B (TN) tile: 128 rows x 32 halves, row stride 48 halves (96B, 16B-aligned)
__device__ __forceinline__ void load_rm(uint32_t sbase, const __nv_bfloat16* G, int ld,
                                        int rowBase, int k0, int tid) {
#pragma unroll
    for (int i = 0; i < 2; i++) {
        int c = tid + i * 256;
        int row = c >> 2, kc = c & 3;
        cpasync16(sbase + (uint32_t)(row * 48 + kc * 8) * 2,
                  G + (size_t)(rowBase + row) * ld + k0 + kc * 8);
    }
}
// B (NN) tile: 32 k-rows x 128 n-cols, row stride 136 halves (272B)
__device__ __forceinline__ void load_nn(uint32_t sbase, const __nv_bfloat16* G, int ld,
                                        int colBase, int k0, int tid) {
#pragma unroll
    for (int i = 0; i < 2; i++) {
        int c = tid + i * 256;
        int kr = c >> 4, nc = c & 15;
        cpasync16(sbase + (uint32_t)(kr * 136 + nc * 8) * 2,
                  G + (size_t)(k0 + kr) * ld + colBase + nc * 8);
    }
}

template <bool TRANSB>
__global__ void __launch_bounds__(256, 1) mma_gemm(MP p) {
    extern __shared__ char smem[];
    const uint32_t sb = smem_u32(smem);
    const int tid = threadIdx.x, lane = tid & 31, wid = tid >> 5;
    const int warpM = wid >> 2, warpN = wid & 3;
    const int z = blockIdx.z, zq = z / p.zdiv, zr = z - zq * p.zdiv;
    const __nv_bfloat16* Ah = p.Ah + (size_t)zq * p.sAz + (size_t)zr * p.sAw;
    const __nv_bfloat16* Al = p.Al + (size_t)zq * p.sAz + (size_t)zr * p.sAw;
    const __nv_bfloat16* Bh = p.Bh + (size_t)zq * p.sBz + (size_t)zr * p.sBw;
    const __nv_bfloat16* Bl = p.Bl + (size_t)zq * p.sBz + (size_t)zr * p.sBw;
    const size_t coff = (size_t)zq * p.sCz + (size_t)zr * p.sCw;
    const int rowBase = blockIdx.y * 128, colBase = blockIdx.x * 128;

    float acc[4][4][4];
#pragma unroll
    for (int i = 0; i < 4; i++)
#pragma unroll
        for (int j = 0; j < 4; j++)
#pragma unroll
            for (int q = 0; q < 4; q++) acc[i][j][q] = 0.f;

    const int nchunk = p.K >> 5;

    auto loadStage = [&](int s, int k0) {
        load_rm(sb + (0 + s) * STG, Ah, p.lda, rowBase, k0, tid);
        load_rm(sb + (2 + s) * STG, Al, p.lda, rowBase, k0, tid);
        if (TRANSB) {
            load_rm(sb + (4 + s) * STG, Bh, p.ldb, colBase, k0, tid);
            load_rm(sb + (6 + s) * STG, Bl, p.ldb, colBase, k0, tid);
        } else {
            load_nn(sb + (4 + s) * STG, Bh, p.ldb, colBase, k0, tid);
            load_nn(sb + (6 + s) * STG, Bl, p.ldb, colBase, k0, tid);
        }
        cpcommit();
    };

    loadStage(0, 0);
    for (int c = 0; c < nchunk; c++) {
        const int s = c & 1;
        if (c + 1 < nchunk) { loadStage(s ^ 1, (c + 1) << 5); cpwait<1>(); }
        else cpwait<0>();
        __syncthreads();

        const uint32_t aH = sb + (0 + s) * STG, aL = sb + (2 + s) * STG;
        const uint32_t bH = sb + (4 + s) * STG, bL = sb + (6 + s) * STG;
#pragma unroll
        for (int kk = 0; kk < 2; kk++) {
            uint32_t ah[4][4], al[4][4], bh[4][2], bl[4][2];
            const int ac = kk * 16 + (lane >> 4) * 8;
            const int ar = warpM * 64 + (lane & 15);
#pragma unroll
            for (int i = 0; i < 4; i++) {
                uint32_t off = (uint32_t)((ar + i * 16) * 48 + ac) * 2;
                ldsm4(ah[i], aH + off);
                ldsm4(al[i], aL + off);
            }
            if (TRANSB) {
#pragma unroll
                for (int jj = 0; jj < 2; jj++) {
                    int br = warpN * 32 + jj * 16 + (lane & 15);
                    uint32_t off = (uint32_t)(br * 48 + ac) * 2;
                    uint32_t r[4], s2[4];
                    ldsm4(r, bH + off);
                    ldsm4(s2, bL + off);
                    bh[jj * 2][0] = r[0]; bh[jj * 2][1] = r[2];
                    bh[jj * 2 + 1][0] = r[1]; bh[jj * 2 + 1][1] = r[3];
                    bl[jj * 2][0] = s2[0]; bl[jj * 2][1] = s2[2];
                    bl[jj * 2 + 1][0] = s2[1]; bl[jj * 2 + 1][1] = s2[3];
                }
            } else {
#pragma unroll
                for (int jj = 0; jj < 2; jj++) {
                    int br = kk * 16 + (lane & 15);
                    int bc = warpN * 32 + jj * 16 + (lane >> 4) * 8;
                    uint32_t off = (uint32_t)(br * 136 + bc) * 2;
                    uint32_t r[4], s2[4];
                    ldsm4t(r, bH + off);
                    ldsm4t(s2, bL + off);
                    bh[jj * 2][0] = r[0]; bh[jj * 2][1] = r[1];
                    bh[jj * 2 + 1][0] = r[2]; bh[jj * 2 + 1][1] = r[3];
                    bl[jj * 2][0] = s2[0]; bl[jj * 2][1] = s2[1];
                    bl[jj * 2 + 1][0] = s2[2]; bl[jj * 2 + 1][1] = s2[3];
                }
            }
#pragma unroll
            for (int i = 0; i < 4; i++)
#pragma unroll
                for (int j = 0; j < 4; j++) {
                    mma16816(acc[i][j], ah[i], bh[j]);
                    mma16816(acc[i][j], ah[i], bl[j]);
                    mma16816(acc[i][j], al[i], bh[j]);
                }
        }
        __syncthreads();
    }

    // epilogue
    const float alpha = p.alpha;
#pragma unroll
    for (int i = 0; i < 4; i++) {
#pragma unroll
        for (int j = 0; j < 4; j++) {
            const int c0 = colBase + warpN * 32 + j * 8 + (lane & 3) * 2;
#pragma unroll
            for (int half = 0; half < 2; half++) {
                const int r = rowBase + warpM * 64 + i * 16 + (lane >> 2) + half * 8;
                float v0 = acc[i][j][half * 2] * alpha;
                float v1 = acc[i][j][half * 2 + 1] * alpha;
                if (p.bias) { v0 += p.bias[c0]; v1 += p.bias[c0 + 1]; }
                const size_t o = coff + (size_t)r * p.ldc + c0;
                if (p.add0) { v0 += p.add0[o]; v1 += p.add0[o + 1]; }
                if (p.add1) { v0 += p.add1[o]; v1 += p.add1[o + 1]; }
                if (p.gelu) {
                    v0 = 0.5f * v0 * (1.0f + erff(v0 * 0.70710678118654752440f));
                    v1 = 0.5f * v1 * (1.0f + erff(v1 * 0.70710678118654752440f));
                }
                if (p.outF) { float2 f2 = make_float2(v0, v1); *(float2*)(p.outF + o) = f2; }
                if (p.outHi) {
                    __nv_bfloat16 h0, l0, h1, l1;
                    split2(v0, h0, l0); split2(v1, h1, l1);
                    __nv_bfloat162 hh; hh.x = h0; hh.y = h1;
                    __nv_bfloat162 ll; ll.x = l0; ll.y = l1;
                    *(__nv_bfloat162*)(p.outHi + o) = hh;
                    *(__nv_bfloat162*)(p.outLo + o) = ll;
                }
            }
        }
    }
}

// ---------------- softmax + head-mean + adjacency ----------------
__device__ __forceinline__ float blockMax256(float v, float* red) {
#pragma unroll
    for (int o = 16; o; o >>= 1) v = fmaxf(v, __shfl_xor_sync(0xffffffffu, v, o));
    if ((threadIdx.x & 31) == 0) red[threadIdx.x >> 5] = v;
    __syncthreads();
    if (threadIdx.x < 32) {
        float x = (threadIdx.x < 8) ? red[threadIdx.x] : -3.4e38f;
#pragma unroll
        for (int o = 4; o; o >>= 1) x = fmaxf(x, __shfl_xor_sync(0xffffffffu, x, o));
        if (threadIdx.x == 0) red[0] = x;
    }
    __syncthreads();
    float r = red[0];
    __syncthreads();
    return r;
}
__device__ __forceinline__ float blockSum256(float v, float* red) {
#pragma unroll
    for (int o = 16; o; o >>= 1) v += __shfl_xor_sync(0xffffffffu, v, o);
    if ((threadIdx.x & 31) == 0) red[threadIdx.x >> 5] = v;
    __syncthreads();
    if (threadIdx.x < 32) {
        float x = (threadIdx.x < 8) ? red[threadIdx.x] : 0.f;
#pragma unroll
        for (int o = 4; o; o >>= 1) x += __shfl_xor_sync(0xffffffffu, x, o);
        if (threadIdx.x == 0) red[0] = x;
    }
    __syncthreads();
    float r = red[0];
    __syncthreads();
    return r;
}

__global__ void __launch_bounds__(256) softmax_kernel() {
    const int i = blockIdx.x, b = blockIdx.y, tid = threadIdx.x;
    __shared__ float red[8];
    float wa[8];
#pragma unroll
    for (int u = 0; u < 8; u++) wa[u] = 0.f;
    for (int h = 0; h < CH; h++) {
        const float* row = g_scores + (((size_t)(b * CH + h) * CS) + i) * CS;
        float vals[8];
        float lmax = -3.4e38f;
#pragma unroll
        for (int u = 0; u < 8; u++) { vals[u] = row[tid + 256 * u]; lmax = fmaxf(lmax, vals[u]); }
        float m = blockMax256(lmax, red);
        float lsum = 0.f;
#pragma unroll
        for (int u = 0; u < 8; u++) { vals[u] = expf(vals[u] - m); lsum += vals[u]; }
        float inv = 1.0f / blockSum256(lsum, red);
#pragma unroll
        for (int u = 0; u < 8; u++) wa[u] += vals[u] * inv;
    }
    float cnt = 0.f;
#pragma unroll
    for (int u = 0; u < 8; u++) {
        float wm = wa[u] * (1.0f / CH);
        wa[u] = wm;
        cnt += (wm > 0.1f) ? 1.f : 0.f;
    }
    float nn = fmaxf(blockSum256(cnt, red), 1.0f);
    float invn = 1.0f / nn;
    size_t base = ((size_t)b * CS + i) * CS;
#pragma unroll
    for (int u = 0; u < 8; u++) {
        int j = tid + 256 * u;
        float wm = wa[u];
        float wk = (wm > 0.1f) ? wm * invn : 0.f;
        __nv_bfloat16 h, l;
        split2(wm, h, l); g_wmh[base + j] = h; g_wml[base + j] = l;
        split2(wk, h, l); g_wkh[base + j] = h; g_wkl[base + j] = l;
    }
}

// ---------------- prep kernels ----------------
__global__ void xsplit_kernel(const float* __restrict__ x) {
    int idx = blockIdx.x * 256 + threadIdx.x;
    if (idx < CBS * CE) {
        __nv_bfloat16 h, l;
        split2(x[idx], h, l);
        g_xh[idx] = h; g_xl[idx] = l;
    }
}
__global__ void wconv_kernel(const float* __restrict__ src, int ldin,
                             __nv_bfloat16* __restrict__ dh, __nv_bfloat16* __restrict__ dl) {
    int idx = blockIdx.x * 256 + threadIdx.x;
    if (idx < CE * CE) {
        int r = idx >> 9, c = idx & 511;
        __nv_bfloat16 h, l;
        split2(src[(size_t)r * ldin + c], h, l);
        dh[idx] = h; dl[idx] = l;
    }
}
__global__ void bm1eff_kernel(const float* __restrict__ Wm1, const float* __restrict__ bm1) {
    int e = blockIdx.x * 256 + threadIdx.x;
    if (e < CE) {
        float s = 0.f;
#pragma unroll
        for (int c = 0; c < CH; c++) s += Wm1[(size_t)e * (CE + CH) + CE + c];
        g_bm1eff[e] = bm1[e] + s * (1.0f / CS);
    }
}

// ---------------- host ----------------
static void run_mm(bool transb,
                   const __nv_bfloat16* Ah, const __nv_bfloat16* Al, int lda,
                   const __nv_bfloat16* Bh, const __nv_bfloat16* Bl, int ldb,
                   int M, int N, int K, float alpha,
                   const float* bias, const float* add0, const float* add1,
                   float* outF, __nv_bfloat16* outHi, __nv_bfloat16* outLo,
                   int ldc, int gelu, int zcount, int zdiv,
                   long long sAz, long long sAw, long long sBz, long long sBw,
                   long long sCz, long long sCw) {
    MP p;
    p.Ah = Ah; p.Al = Al; p.Bh = Bh; p.Bl = Bl;
    p.lda = lda; p.ldb = ldb; p.K = K; p.alpha = alpha;
    p.bias = bias; p.add0 = add0; p.add1 = add1;
    p.outF = outF; p.outHi = outHi; p.outLo = outLo;
    p.ldc = ldc; p.gelu = gelu; p.zdiv = zdiv;
    p.sAz = sAz; p.sAw = sAw; p.sBz = sBz; p.sBw = sBw; p.sCz = sCz; p.sCw = sCw;
    dim3 grid(N / 128, M / 128, zcount);
    if (transb) mma_gemm<true><<<grid, 256, SMEM_BYTES>>>(p);
    else        mma_gemm<false><<<grid, 256, SMEM_BYTES>>>(p);
}

extern "C" void kernel_launch(void* const* d_in, const int* in_sizes, int n_in,
                              void* d_out, int out_size) {
    const float* x   = (const float*)d_in[0];
    const float* Wq  = (const float*)d_in[1];
    const float* bq  = (const float*)d_in[2];
    const float* Wk  = (const float*)d_in[3];
    const float* bk  = (const float*)d_in[4];
    const float* Wv  = (const float*)d_in[5];
    const float* bv  = (const float*)d_in[6];
    const float* Wm1 = (const float*)d_in[7];
    const float* bm1 = (const float*)d_in[8];
    const float* Wm2 = (const float*)d_in[9];
    const float* bm2 = (const float*)d_in[10];
    const float* Wo  = (const float*)d_in[11];
    const float* bo  = (const float*)d_in[12];
    float* out = (float*)d_out;

    cudaFuncSetAttribute(mma_gemm<true>,  cudaFuncAttributeMaxDynamicSharedMemorySize, SMEM_BYTES);
    cudaFuncSetAttribute(mma_gemm<false>, cudaFuncAttributeMaxDynamicSharedMemorySize, SMEM_BYTES);

    float *sc, *msg, *att, *b1e;
    __nv_bfloat16 *xh, *xl, *qh, *ql, *kh, *kl, *vh, *vl;
    __nv_bfloat16 *t1h, *t1l, *t2h, *t2l, *wmh, *wml, *wkh, *wkl, *Wh, *Wl;
    cudaGetSymbolAddress((void**)&sc, g_scores);
    cudaGetSymbolAddress((void**)&msg, g_msg);
    cudaGetSymbolAddress((void**)&att, g_att);
    cudaGetSymbolAddress((void**)&b1e, g_bm1eff);
    cudaGetSymbolAddress((void**)&xh, g_xh);   cudaGetSymbolAddress((void**)&xl, g_xl);
    cudaGetSymbolAddress((void**)&qh, g_qh);   cudaGetSymbolAddress((void**)&ql, g_ql);
    cudaGetSymbolAddress((void**)&kh, g_kh);   cudaGetSymbolAddress((void**)&kl, g_kl);
    cudaGetSymbolAddress((void**)&vh, g_vh);   cudaGetSymbolAddress((void**)&vl, g_vl);
    cudaGetSymbolAddress((void**)&t1h, g_t1h); cudaGetSymbolAddress((void**)&t1l, g_t1l);
    cudaGetSymbolAddress((void**)&t2h, g_t2h); cudaGetSymbolAddress((void**)&t2l, g_t2l);
    cudaGetSymbolAddress((void**)&wmh, g_wmh); cudaGetSymbolAddress((void**)&wml, g_wml);
    cudaGetSymbolAddress((void**)&wkh, g_wkh); cudaGetSymbolAddress((void**)&wkl, g_wkl);
    cudaGetSymbolAddress((void**)&Wh, g_Wh);   cudaGetSymbolAddress((void**)&Wl, g_Wl);

    const long long SE = (long long)CS * CE;
    const long long SS = (long long)CS * CS;
    const int WN = CE * CE;

    // prep: splits + effective bm1
    xsplit_kernel<<<(CBS * CE + 255) / 256, 256>>>(x);
    int wgrid = (CE * CE + 255) / 256;
    wconv_kernel<<<wgrid, 256>>>(Wq, CE, Wh + 0 * WN, Wl + 0 * WN);
    wconv_kernel<<<wgrid, 256>>>(Wk, CE, Wh + 1 * WN, Wl + 1 * WN);
    wconv_kernel<<<wgrid, 256>>>(Wv, CE, Wh + 2 * WN, Wl + 2 * WN);
    wconv_kernel<<<wgrid, 256>>>(Wm1, CE + CH, Wh + 3 * WN, Wl + 3 * WN);
    wconv_kernel<<<wgrid, 256>>>(Wm2, CE, Wh + 4 * WN, Wl + 4 * WN);
    wconv_kernel<<<wgrid, 256>>>(Wo, CE, Wh + 5 * WN, Wl + 5 * WN);
    bm1eff_kernel<<<2, 256>>>(Wm1, bm1);

    // q, k, v projections (bf16-split outputs, row-major)
    run_mm(true, xh, xl, CE, Wh + 0 * WN, Wl + 0 * WN, CE, CBS, CE, CE, 1.f, bq,
           nullptr, nullptr, nullptr, qh, ql, CE, 0, 1, 1, 0, 0, 0, 0, 0, 0);
    run_mm(true, xh, xl, CE, Wh + 1 * WN, Wl + 1 * WN, CE, CBS, CE, CE, 1.f, bk,
           nullptr, nullptr, nullptr, kh, kl, CE, 0, 1, 1, 0, 0, 0, 0, 0, 0);
    run_mm(true, xh, xl, CE, Wh + 2 * WN, Wl + 2 * WN, CE, CBS, CE, CE, 1.f, bv,
           nullptr, nullptr, nullptr, vh, vl, CE, 0, 1, 1, 0, 0, 0, 0, 0, 0);

    // scores = 0.125 * q_h @ k_h^T  (z = b*8 + h)
    run_mm(true, qh, ql, CE, kh, kl, CE, CS, CS, 64, 0.125f, nullptr,
           nullptr, nullptr, sc, nullptr, nullptr, CS, 0,
           CB * CH, CH, SE, 64, SE, 64, (long long)CH * SS, SS);

    // softmax / adjacency
    {
        dim3 g(CS, CB);
        softmax_kernel<<<g, 256>>>();
    }

    // messages = wk @ x (NN), attended = wm @ v (NN)
    run_mm(false, wkh, wkl, CS, xh, xl, CE, CS, CE, CS, 1.f, nullptr,
           nullptr, nullptr, msg, nullptr, nullptr, CE, 0,
           CB, 1, SS, 0, SE, 0, SE, 0);
    run_mm(false, wmh, wml, CS, vh, vl, CE, CS, CE, CS, 1.f, nullptr,
           nullptr, nullptr, att, nullptr, nullptr, CE, 0,
           CB, 1, SS, 0, SE, 0, SE, 0);

    // t1 = gelu(x @ Wm1'^T + bm1eff)
    run_mm(true, xh, xl, CE, Wh + 3 * WN, Wl + 3 * WN, CE, CBS, CE, CE, 1.f, b1e,
           nullptr, nullptr, nullptr, t1h, t1l, CE, 1, 1, 1, 0, 0, 0, 0, 0, 0);

    // t2 = t1 @ Wm2^T + bm2 + msg + att
    run_mm(true, t1h, t1l, CE, Wh + 4 * WN, Wl + 4 * WN, CE, CBS, CE, CE, 1.f, bm2,
           msg, att, nullptr, t2h, t2l, CE, 0, 1, 1, 0, 0, 0, 0, 0, 0);

    // out = t2 @ Wo^T + bo
    run_mm(true, t2h, t2l, CE, Wh + 5 * WN, Wl + 5 * WN, CE, CBS, CE, CE, 1.f, bo,
           nullptr, nullptr, out, nullptr, nullptr, CE, 0, 1, 1, 0, 0, 0, 0, 0, 0);
}

// round 7
// speedup vs baseline: 2.6596x; 1.0422x over previous
#include <cuda_runtime.h>
#include <cuda_bf16.h>
#include <cstdint>
#include <math.h>

constexpr int CB = 2, CS = 2048, CE = 512, CH = 8, CBS = CB * CS;

// ---------------- scratch (device globals; allocation-free) ----------------
__device__ __align__(128) float g_scores[(size_t)CB * CH * CS * CS];  // 268 MB
__device__ __align__(128) __nv_bfloat16 g_xh[CBS * CE], g_xl[CBS * CE];
__device__ __align__(128) __nv_bfloat16 g_qh[CBS * CE], g_ql[CBS * CE];
__device__ __align__(128) __nv_bfloat16 g_kh[CBS * CE], g_kl[CBS * CE];
// stacked [x ; v] per batch: [b][0..2047]=x, [b][2048..4095]=v, width CE
__device__ __align__(128) __nv_bfloat16 g_xvh[(size_t)CB * 2 * CS * CE], g_xvl[(size_t)CB * 2 * CS * CE];
__device__ __align__(128) __nv_bfloat16 g_t1h[CBS * CE], g_t1l[CBS * CE];
__device__ __align__(128) __nv_bfloat16 g_t2h[CBS * CE], g_t2l[CBS * CE];
// combined weights [b][i][0..2047]=wk, [b][i][2048..4095]=wm
__device__ __align__(128) __nv_bfloat16 g_wh[(size_t)CB * CS * 2 * CS], g_wl[(size_t)CB * CS * 2 * CS];
__device__ __align__(128) __nv_bfloat16 g_Wh[6 * CE * CE], g_Wl[6 * CE * CE];
__device__ __align__(128) float g_msgatt[CBS * CE], g_bm1eff[CE];

// ---------------- low-level helpers ----------------
__device__ __forceinline__ uint32_t smem_u32(const void* p) {
    uint32_t a;
    asm("{ .reg .u64 t; cvta.to.shared.u64 t, %1; cvt.u32.u64 %0, t; }" : "=r"(a) : "l"(p));
    return a;
}
__device__ __forceinline__ void cpasync16(uint32_t dst, const void* src) {
    asm volatile("cp.async.ca.shared.global [%0], [%1], 16;" :: "r"(dst), "l"(src));
}
__device__ __forceinline__ void cpcommit() { asm volatile("cp.async.commit_group;"); }
template <int N> __device__ __forceinline__ void cpwait() {
    asm volatile("cp.async.wait_group %0;" :: "n"(N));
}
__device__ __forceinline__ void ldsm4(uint32_t* r, uint32_t a) {
    asm volatile("ldmatrix.sync.aligned.m8n8.x4.shared.b16 {%0,%1,%2,%3}, [%4];"
                 : "=r"(r[0]), "=r"(r[1]), "=r"(r[2]), "=r"(r[3]) : "r"(a));
}
__device__ __forceinline__ void ldsm4t(uint32_t* r, uint32_t a) {
    asm volatile("ldmatrix.sync.aligned.m8n8.x4.trans.shared.b16 {%0,%1,%2,%3}, [%4];"
                 : "=r"(r[0]), "=r"(r[1]), "=r"(r[2]), "=r"(r[3]) : "r"(a));
}
__device__ __forceinline__ void mma16816(float* c, const uint32_t* a, const uint32_t* b) {
    asm volatile(
        "mma.sync.aligned.m16n8k16.row.col.f32.bf16.bf16.f32 "
        "{%0,%1,%2,%3}, {%4,%5,%6,%7}, {%8,%9}, {%0,%1,%2,%3};"
        : "+f"(c[0]), "+f"(c[1]), "+f"(c[2]), "+f"(c[3])
        : "r"(a[0]), "r"(a[1]), "r"(a[2]), "r"(a[3]), "r"(b[0]), "r"(b[1]));
}
__device__ __forceinline__ void split2(float v, __nv_bfloat16& h, __nv_bfloat16& l) {
    h = __float2bfloat16(v);
    l = __float2bfloat16(v - __bfloat162float(h));
}

// ---------------- bf16-split tensor-core GEMM ----------------
// C = alpha * A @ op(B) (+bias)(+add0)(gelu). A:[M][K] rm. TRANSB: B:[N][K] rm, else B:[K][N] rm.
// CTA tile 64x128, K-chunk 32, 2-stage cp.async pipeline, 8 warps (2x4) of 32x32.
// Output row mapping: o = coff + (r>>11)*segA + segB + (r&2047)*ldc + c  (default segA=2048*ldc, segB=0)
struct MP {
    const __nv_bfloat16 *Ah, *Al, *Bh, *Bl;
    int lda, ldb, K;
    float alpha;
    const float *bias, *add0;
    float* outF;
    __nv_bfloat16 *outHi, *outLo;
    int ldc, gelu, zdiv;
    long long sAz, sAw, sBz, sBw, sCz, sCw;
    long long segA, segB;
};

constexpr int STG_A = 6144;    // 64 rows x 48 halves x 2B
constexpr int STG_B = 12288;   // max(128x48, 32x136) halves x 2B
constexpr int STAGE = 2 * STG_A + 2 * STG_B;  // 36864
constexpr int SMEM_BYTES = 2 * STAGE;          // 73728

// A tile: 64 rows x 32 halves, row stride 48 halves (96B); 1 chunk/thread
__device__ __forceinline__ void load_a(uint32_t sbase, const __nv_bfloat16* G, int ld,
                                       int rowBase, int k0, int tid) {
    int row = tid >> 2, kc = tid & 3;
    cpasync16(sbase + (uint32_t)(row * 48 + kc * 8) * 2,
              G + (size_t)(rowBase + row) * ld + k0 + kc * 8);
}
// B (TN) tile: 128 rows x 32 halves, row stride 48 halves; 2 chunks/thread
__device__ __forceinline__ void load_bt(uint32_t sbase, const __nv_bfloat16* G, int ld,
                                        int colBase, int k0, int tid) {
#pragma unroll
    for (int i = 0; i < 2; i++) {
        int c = tid + i * 256;
        int row = c >> 2, kc = c & 3;
        cpasync16(sbase + (uint32_t)(row * 48 + kc * 8) * 2,
                  G + (size_t)(colBase + row) * ld + k0 + kc * 8);
    }
}
// B (NN) tile: 32 k-rows x 128 n-cols, row stride 136 halves (272B); 2 chunks/thread
__device__ __forceinline__ void load_bn(uint32_t sbase, const __nv_bfloat16* G, int ld,
                                        int colBase, int k0, int tid) {
#pragma unroll
    for (int i = 0; i < 2; i++) {
        int c = tid + i * 256;
        int kr = c >> 4, nc = c & 15;
        cpasync16(sbase + (uint32_t)(kr * 136 + nc * 8) * 2,
                  G + (size_t)(k0 + kr) * ld + colBase + nc * 8);
    }
}

template <bool TRANSB>
__global__ void __launch_bounds__(256, 2) mma_gemm(MP p) {
    extern __shared__ char smem[];
    const uint32_t sb = smem_u32(smem);
    const int tid = threadIdx.x, lane = tid & 31, wid = tid >> 5;
    const int warpM = wid >> 2, warpN = wid & 3;
    const int z = blockIdx.z, zq = z / p.zdiv, zr = z - zq * p.zdiv;
    const __nv_bfloat16* Ah = p.Ah + (size_t)zq * p.sAz + (size_t)zr * p.sAw;
    const __nv_bfloat16* Al = p.Al + (size_t)zq * p.sAz + (size_t)zr * p.sAw;
    const __nv_bfloat16* Bh = p.Bh + (size_t)zq * p.sBz + (size_t)zr * p.sBw;
    const __nv_bfloat16* Bl = p.Bl + (size_t)zq * p.sBz + (size_t)zr * p.sBw;
    const size_t coff = (size_t)zq * p.sCz + (size_t)zr * p.sCw;
    const int rowBase = blockIdx.y * 64, colBase = blockIdx.x * 128;

    float acc[2][4][4];
#pragma unroll
    for (int i = 0; i < 2; i++)
#pragma unroll
        for (int j = 0; j < 4; j++)
#pragma unroll
            for (int q = 0; q < 4; q++) acc[i][j][q] = 0.f;

    const int nchunk = p.K >> 5;

    auto loadStage = [&](int s, int k0) {
        uint32_t base = sb + s * STAGE;
        load_a(base, Ah, p.lda, rowBase, k0, tid);
        load_a(base + STG_A, Al, p.lda, rowBase, k0, tid);
        if (TRANSB) {
            load_bt(base + 2 * STG_A, Bh, p.ldb, colBase, k0, tid);
            load_bt(base + 2 * STG_A + STG_B, Bl, p.ldb, colBase, k0, tid);
        } else {
            load_bn(base + 2 * STG_A, Bh, p.ldb, colBase, k0, tid);
            load_bn(base + 2 * STG_A + STG_B, Bl, p.ldb, colBase, k0, tid);
        }
        cpcommit();
    };

    loadStage(0, 0);
    for (int c = 0; c < nchunk; c++) {
        const int s = c & 1;
        if (c + 1 < nchunk) { loadStage(s ^ 1, (c + 1) << 5); cpwait<1>(); }
        else cpwait<0>();
        __syncthreads();

        const uint32_t base = sb + s * STAGE;
        const uint32_t aH = base, aL = base + STG_A;
        const uint32_t bH = base + 2 * STG_A, bL = base + 2 * STG_A + STG_B;
#pragma unroll
        for (int kk = 0; kk < 2; kk++) {
            uint32_t ah[2][4], al[2][4], bh[4][2], bl[4][2];
            const int ac = kk * 16 + (lane >> 4) * 8;
            const int ar = warpM * 32 + (lane & 15);
#pragma unroll
            for (int i = 0; i < 2; i++) {
                uint32_t off = (uint32_t)((ar + i * 16) * 48 + ac) * 2;
                ldsm4(ah[i], aH + off);
                ldsm4(al[i], aL + off);
            }
            if (TRANSB) {
#pragma unroll
                for (int jj = 0; jj < 2; jj++) {
                    int br = warpN * 32 + jj * 16 + (lane & 15);
                    uint32_t off = (uint32_t)(br * 48 + ac) * 2;
                    uint32_t r[4], s2[4];
                    ldsm4(r, bH + off);
                    ldsm4(s2, bL + off);
                    bh[jj * 2][0] = r[0]; bh[jj * 2][1] = r[2];
                    bh[jj * 2 + 1][0] = r[1]; bh[jj * 2 + 1][1] = r[3];
                    bl[jj * 2][0] = s2[0]; bl[jj * 2][1] = s2[2];
                    bl[jj * 2 + 1][0] = s2[1]; bl[jj * 2 + 1][1] = s2[3];
                }
            } else {
#pragma unroll
                for (int jj = 0; jj < 2; jj++) {
                    int br = kk * 16 + (lane & 15);
                    int bc = warpN * 32 + jj * 16 + (lane >> 4) * 8;
                    uint32_t off = (uint32_t)(br * 136 + bc) * 2;
                    uint32_t r[4], s2[4];
                    ldsm4t(r, bH + off);
                    ldsm4t(s2, bL + off);
                    bh[jj * 2][0] = r[0]; bh[jj * 2][1] = r[1];
                    bh[jj * 2 + 1][0] = r[2]; bh[jj * 2 + 1][1] = r[3];
                    bl[jj * 2][0] = s2[0]; bl[jj * 2][1] = s2[1];
                    bl[jj * 2 + 1][0] = s2[2]; bl[jj * 2 + 1][1] = s2[3];
                }
            }
#pragma unroll
            for (int i = 0; i < 2; i++)
#pragma unroll
                for (int j = 0; j < 4; j++) {
                    mma16816(acc[i][j], ah[i], bh[j]);
                    mma16816(acc[i][j], ah[i], bl[j]);
                    mma16816(acc[i][j], al[i], bh[j]);
                }
        }
        __syncthreads();
    }

    // epilogue
    const float alpha = p.alpha;
#pragma unroll
    for (int i = 0; i < 2; i++) {
#pragma unroll
        for (int j = 0; j < 4; j++) {
            const int c0 = colBase + warpN * 32 + j * 8 + (lane & 3) * 2;
#pragma unroll
            for (int half = 0; half < 2; half++) {
                const int r = rowBase + warpM * 32 + i * 16 + (lane >> 2) + half * 8;
                float v0 = acc[i][j][half * 2] * alpha;
                float v1 = acc[i][j][half * 2 + 1] * alpha;
                if (p.bias) { v0 += p.bias[c0]; v1 += p.bias[c0 + 1]; }
                const size_t o = coff + (size_t)(r >> 11) * p.segA + p.segB
                               + (size_t)(r & 2047) * p.ldc + c0;
                if (p.add0) { v0 += p.add0[o]; v1 += p.add0[o + 1]; }
                if (p.gelu) {
                    v0 = 0.5f * v0 * (1.0f + erff(v0 * 0.70710678118654752440f));
                    v1 = 0.5f * v1 * (1.0f + erff(v1 * 0.70710678118654752440f));
                }
                if (p.outF) { float2 f2 = make_float2(v0, v1); *(float2*)(p.outF + o) = f2; }
                if (p.outHi) {
                    __nv_bfloat16 h0, l0, h1, l1;
                    split2(v0, h0, l0); split2(v1, h1, l1);
                    __nv_bfloat162 hh; hh.x = h0; hh.y = h1;
                    __nv_bfloat162 ll; ll.x = l0; ll.y = l1;
                    *(__nv_bfloat162*)(p.outHi + o) = hh;
                    *(__nv_bfloat162*)(p.outLo + o) = ll;
                }
            }
        }
    }
}

// ---------------- softmax + head-mean + adjacency ----------------
__device__ __forceinline__ float blockMax256(float v, float* red) {
#pragma unroll
    for (int o = 16; o; o >>= 1) v = fmaxf(v, __shfl_xor_sync(0xffffffffu, v, o));
    if ((threadIdx.x & 31) == 0) red[threadIdx.x >> 5] = v;
    __syncthreads();
    if (threadIdx.x < 32) {
        float x = (threadIdx.x < 8) ? red[threadIdx.x] : -3.4e38f;
#pragma unroll
        for (int o = 4; o; o >>= 1) x = fmaxf(x, __shfl_xor_sync(0xffffffffu, x, o));
        if (threadIdx.x == 0) red[0] = x;
    }
    __syncthreads();
    float r = red[0];
    __syncthreads();
    return r;
}
__device__ __forceinline__ float blockSum256(float v, float* red) {
#pragma unroll
    for (int o = 16; o; o >>= 1) v += __shfl_xor_sync(0xffffffffu, v, o);
    if ((threadIdx.x & 31) == 0) red[threadIdx.x >> 5] = v;
    __syncthreads();
    if (threadIdx.x < 32) {
        float x = (threadIdx.x < 8) ? red[threadIdx.x] : 0.f;
#pragma unroll
        for (int o = 4; o; o >>= 1) x += __shfl_xor_sync(0xffffffffu, x, o);
        if (threadIdx.x == 0) red[0] = x;
    }
    __syncthreads();
    float r = red[0];
    __syncthreads();
    return r;
}

__global__ void __launch_bounds__(256) softmax_kernel() {
    const int i = blockIdx.x, b = blockIdx.y, tid = threadIdx.x;
    __shared__ float red[8];
    float wa[8];
#pragma unroll
    for (int u = 0; u < 8; u++) wa[u] = 0.f;
    for (int h = 0; h < CH; h++) {
        const float* row = g_scores + (((size_t)(b * CH + h) * CS) + i) * CS;
        float vals[8];
        float lmax = -3.4e38f;
#pragma unroll
        for (int u = 0; u < 8; u++) { vals[u] = row[tid + 256 * u]; lmax = fmaxf(lmax, vals[u]); }
        float m = blockMax256(lmax, red);
        float lsum = 0.f;
#pragma unroll
        for (int u = 0; u < 8; u++) { vals[u] = expf(vals[u] - m); lsum += vals[u]; }
        float inv = 1.0f / blockSum256(lsum, red);
#pragma unroll
        for (int u = 0; u < 8; u++) wa[u] += vals[u] * inv;
    }
    float cnt = 0.f;
#pragma unroll
    for (int u = 0; u < 8; u++) {
        float wm = wa[u] * (1.0f / CH);
        wa[u] = wm;
        cnt += (wm > 0.1f) ? 1.f : 0.f;
    }
    float nn = fmaxf(blockSum256(cnt, red), 1.0f);
    float invn = 1.0f / nn;
    // combined A row: [wk(0..2047) | wm(2048..4095)]
    size_t base = ((size_t)b * CS + i) * (size_t)(2 * CS);
#pragma unroll
    for (int u = 0; u < 8; u++) {
        int j = tid + 256 * u;
        float wm = wa[u];
        float wk = (wm > 0.1f) ? wm * invn : 0.f;
        __nv_bfloat16 h, l;
        split2(wk, h, l); g_wh[base + j] = h;        g_wl[base + j] = l;
        split2(wm, h, l); g_wh[base + 2048 + j] = h; g_wl[base + 2048 + j] = l;
    }
}

// ---------------- prep kernels ----------------
__global__ void xsplit_kernel(const float* __restrict__ x) {
    int idx = blockIdx.x * 256 + threadIdx.x;
    if (idx < CBS * CE) {
        __nv_bfloat16 h, l;
        split2(x[idx], h, l);
        g_xh[idx] = h; g_xl[idx] = l;
        // also into stacked [x;v]: batch b occupies 2*CS*CE, x at segment 0
        int b = idx >> 20;                 // CS*CE = 2^20
        int within = idx & ((CS * CE) - 1);
        size_t o = (size_t)b * (2 * CS * CE) + within;
        g_xvh[o] = h; g_xvl[o] = l;
    }
}
__global__ void wconv_kernel(const float* __restrict__ src, int ldin,
                             __nv_bfloat16* __restrict__ dh, __nv_bfloat16* __restrict__ dl) {
    int idx = blockIdx.x * 256 + threadIdx.x;
    if (idx < CE * CE) {
        int r = idx >> 9, c = idx & 511;
        __nv_bfloat16 h, l;
        split2(src[(size_t)r * ldin + c], h, l);
        dh[idx] = h; dl[idx] = l;
    }
}
__global__ void bm1eff_kernel(const float* __restrict__ Wm1, const float* __restrict__ bm1) {
    int e = blockIdx.x * 256 + threadIdx.x;
    if (e < CE) {
        float s = 0.f;
#pragma unroll
        for (int c = 0; c < CH; c++) s += Wm1[(size_t)e * (CE + CH) + CE + c];
        g_bm1eff[e] = bm1[e] + s * (1.0f / CS);
    }
}

// ---------------- host ----------------
static void run_mm(bool transb,
                   const __nv_bfloat16* Ah, const __nv_bfloat16* Al, int lda,
                   const __nv_bfloat16* Bh, const __nv_bfloat16* Bl, int ldb,
                   int M, int N, int K, float alpha,
                   const float* bias, const float* add0,
                   float* outF, __nv_bfloat16* outHi, __nv_bfloat16* outLo,
                   int ldc, int gelu, int zcount, int zdiv,
                   long long sAz, long long sAw, long long sBz, long long sBw,
                   long long sCz, long long sCw,
                   long long segA = -1, long long segB = 0) {
    MP p;
    p.Ah = Ah; p.Al = Al; p.Bh = Bh; p.Bl = Bl;
    p.lda = lda; p.ldb = ldb; p.K = K; p.alpha = alpha;
    p.bias = bias; p.add0 = add0;
    p.outF = outF; p.outHi = outHi; p.outLo = outLo;
    p.ldc = ldc; p.gelu = gelu; p.zdiv = zdiv;
    p.sAz = sAz; p.sAw = sAw; p.sBz = sBz; p.sBw = sBw; p.sCz = sCz; p.sCw = sCw;
    p.segA = (segA < 0) ? (long long)2048 * ldc : segA;
    p.segB = segB;
    dim3 grid(N / 128, M / 64, zcount);
    if (transb) mma_gemm<true><<<grid, 256, SMEM_BYTES>>>(p);
    else        mma_gemm<false><<<grid, 256, SMEM_BYTES>>>(p);
}

extern "C" void kernel_launch(void* const* d_in, const int* in_sizes, int n_in,
                              void* d_out, int out_size) {
    const float* x   = (const float*)d_in[0];
    const float* Wq  = (const float*)d_in[1];
    const float* bq  = (const float*)d_in[2];
    const float* Wk  = (const float*)d_in[3];
    const float* bk  = (const float*)d_in[4];
    const float* Wv  = (const float*)d_in[5];
    const float* bv  = (const float*)d_in[6];
    const float* Wm1 = (const float*)d_in[7];
    const float* bm1 = (const float*)d_in[8];
    const float* Wm2 = (const float*)d_in[9];
    const float* bm2 = (const float*)d_in[10];
    const float* Wo  = (const float*)d_in[11];
    const float* bo  = (const float*)d_in[12];
    float* out = (float*)d_out;

    cudaFuncSetAttribute(mma_gemm<true>,  cudaFuncAttributeMaxDynamicSharedMemorySize, SMEM_BYTES);
    cudaFuncSetAttribute(mma_gemm<false>, cudaFuncAttributeMaxDynamicSharedMemorySize, SMEM_BYTES);

    float *sc, *ma, *b1e;
    __nv_bfloat16 *xh, *xl, *qh, *ql, *kh, *kl, *xvh, *xvl;
    __nv_bfloat16 *t1h, *t1l, *t2h, *t2l, *wh, *wl, *Wh, *Wl;
    cudaGetSymbolAddress((void**)&sc, g_scores);
    cudaGetSymbolAddress((void**)&ma, g_msgatt);
    cudaGetSymbolAddress((void**)&b1e, g_bm1eff);
    cudaGetSymbolAddress((void**)&xh, g_xh);   cudaGetSymbolAddress((void**)&xl, g_xl);
    cudaGetSymbolAddress((void**)&qh, g_qh);   cudaGetSymbolAddress((void**)&ql, g_ql);
    cudaGetSymbolAddress((void**)&kh, g_kh);   cudaGetSymbolAddress((void**)&kl, g_kl);
    cudaGetSymbolAddress((void**)&xvh, g_xvh); cudaGetSymbolAddress((void**)&xvl, g_xvl);
    cudaGetSymbolAddress((void**)&t1h, g_t1h); cudaGetSymbolAddress((void**)&t1l, g_t1l);
    cudaGetSymbolAddress((void**)&t2h, g_t2h); cudaGetSymbolAddress((void**)&t2l, g_t2l);
    cudaGetSymbolAddress((void**)&wh, g_wh);   cudaGetSymbolAddress((void**)&wl, g_wl);
    cudaGetSymbolAddress((void**)&Wh, g_Wh);   cudaGetSymbolAddress((void**)&Wl, g_Wl);

    const long long SE = (long long)CS * CE;
    const long long SS = (long long)CS * CS;
    const int WN = CE * CE;

    // prep: splits + effective bm1
    xsplit_kernel<<<(CBS * CE + 255) / 256, 256>>>(x);
    int wgrid = (CE * CE + 255) / 256;
    wconv_kernel<<<wgrid, 256>>>(Wq, CE, Wh + 0 * WN, Wl + 0 * WN);
    wconv_kernel<<<wgrid, 256>>>(Wk, CE, Wh + 1 * WN, Wl + 1 * WN);
    wconv_kernel<<<wgrid, 256>>>(Wv, CE, Wh + 2 * WN, Wl + 2 * WN);
    wconv_kernel<<<wgrid, 256>>>(Wm1, CE + CH, Wh + 3 * WN, Wl + 3 * WN);
    wconv_kernel<<<wgrid, 256>>>(Wm2, CE, Wh + 4 * WN, Wl + 4 * WN);
    wconv_kernel<<<wgrid, 256>>>(Wo, CE, Wh + 5 * WN, Wl + 5 * WN);
    bm1eff_kernel<<<2, 256>>>(Wm1, bm1);

    // q, k projections (row-major); v projection written into stacked [x;v] (segment 1)
    run_mm(true, xh, xl, CE, Wh + 0 * WN, Wl + 0 * WN, CE, CBS, CE, CE, 1.f, bq,
           nullptr, nullptr, qh, ql, CE, 0, 1, 1, 0, 0, 0, 0, 0, 0);
    run_mm(true, xh, xl, CE, Wh + 1 * WN, Wl + 1 * WN, CE, CBS, CE, CE, 1.f, bk,
           nullptr, nullptr, kh, kl, CE, 0, 1, 1, 0, 0, 0, 0, 0, 0);
    run_mm(true, xh, xl, CE, Wh + 2 * WN, Wl + 2 * WN, CE, CBS, CE, CE, 1.f, bv,
           nullptr, nullptr, xvh, xvl, CE, 0, 1, 1, 0, 0, 0, 0, 0, 0,
           (long long)2 * CS * CE /*segA: batch block*/, (long long)CS * CE /*segB: v segment*/);

    // scores = 0.125 * q_h @ k_h^T  (z = b*8 + h)
    run_mm(true, qh, ql, CE, kh, kl, CE, CS, CS, 64, 0.125f, nullptr,
           nullptr, sc, nullptr, nullptr, CS, 0,
           CB * CH, CH, SE, 64, SE, 64, (long long)CH * SS, SS);

    // softmax / adjacency -> combined [wk | wm]
    {
        dim3 g(CS, CB);
        softmax_kernel<<<g, 256>>>();
    }

    // msg+att = [wk|wm] @ [x;v]   (K = 4096, per batch)
    run_mm(false, wh, wl, 2 * CS, xvh, xvl, CE, CS, CE, 2 * CS, 1.f, nullptr,
           nullptr, ma, nullptr, nullptr, CE, 0,
           CB, 1, (long long)CS * 2 * CS, 0, (long long)2 * CS * CE, 0, SE, 0);

    // t1 = gelu(x @ Wm1'^T + bm1eff)
    run_mm(true, xh, xl, CE, Wh + 3 * WN, Wl + 3 * WN, CE, CBS, CE, CE, 1.f, b1e,
           nullptr, nullptr, t1h, t1l, CE, 1, 1, 1, 0, 0, 0, 0, 0, 0);

    // t2 = t1 @ Wm2^T + bm2 + (msg+att)
    run_mm(true, t1h, t1l, CE, Wh + 4 * WN, Wl + 4 * WN, CE, CBS, CE, CE, 1.f, bm2,
           ma, nullptr, t2h, t2l, CE, 0, 1, 1, 0, 0, 0, 0, 0, 0);

    // out = t2 @ Wo^T + bo
    run_mm(true, t2h, t2l, CE, Wh + 5 * WN, Wl + 5 * WN, CE, CBS, CE, CE, 1.f, bo,
           nullptr, out, nullptr, nullptr, CE, 0, 1, 1, 0, 0, 0, 0, 0, 0);
}